// round 1
// baseline (speedup 1.0000x reference)
#include <cuda_runtime.h>

// Problem dims
#define SEQ   1024
#define CDIM  1280
#define NHEAD 20
#define HDIM  64
#define M2    2048      // 2 distinct batches * SEQ
#define BHPAIRS 40      // 2 * NHEAD

// Scratch (allocation-free rule: __device__ globals)
__device__ float g_q[M2 * CDIM];
__device__ float g_k[M2 * CDIM];
__device__ float g_v[M2 * CDIM];
__device__ float g_attn[M2 * CDIM];
__device__ float g_scores[(size_t)BHPAIRS * SEQ * SEQ];   // 40 * 1024 * 1024 floats

// ---------------------------------------------------------------------------
// Kernel 1: fused QKV projection for batches 0 and 4 only.
// C[r, n] = sum_k X[srow(r), k] * W[k, n]
// 128x128 block tile, BK=16, 256 threads, 8x8 per-thread register tile.
// ---------------------------------------------------------------------------
__global__ __launch_bounds__(256, 2) void qkv_gemm(
    const float* __restrict__ X,
    const float* __restrict__ Wq,
    const float* __restrict__ Wk,
    const float* __restrict__ Wv)
{
    const float* W  = (blockIdx.z == 0) ? Wq : (blockIdx.z == 1) ? Wk : Wv;
    float*       Ou = (blockIdx.z == 0) ? g_q : (blockIdx.z == 1) ? g_k : g_v;

    __shared__ float As[16][128];   // transposed: As[k][m]
    __shared__ float Bs[16][128];   // Bs[k][n]

    const int bm  = blockIdx.y * 128;
    const int bn  = blockIdx.x * 128;
    const int tid = threadIdx.x;
    const int tx  = tid & 15;
    const int ty  = tid >> 4;

    float acc[8][8];
    #pragma unroll
    for (int i = 0; i < 8; i++)
        #pragma unroll
        for (int j = 0; j < 8; j++) acc[i][j] = 0.f;

    const int arow0 = tid >> 2;   // 0..63
    const int ac4   = tid & 3;    // 0..3
    const int bk0   = tid >> 5;   // 0..7
    const int bc4   = tid & 31;   // 0..31

    for (int k0 = 0; k0 < CDIM; k0 += 16) {
        #pragma unroll
        for (int half = 0; half < 2; half++) {
            int row  = arow0 + half * 64;
            int grow = bm + row;
            int srow = (grow < SEQ) ? grow : grow + 3 * SEQ;  // batch 0 or batch 4
            float4 v = *reinterpret_cast<const float4*>(
                &X[(size_t)srow * CDIM + k0 + ac4 * 4]);
            As[ac4 * 4 + 0][row] = v.x;
            As[ac4 * 4 + 1][row] = v.y;
            As[ac4 * 4 + 2][row] = v.z;
            As[ac4 * 4 + 3][row] = v.w;
        }
        #pragma unroll
        for (int half = 0; half < 2; half++) {
            int kr = bk0 + half * 8;
            float4 v = *reinterpret_cast<const float4*>(
                &W[(size_t)(k0 + kr) * CDIM + bn + bc4 * 4]);
            *reinterpret_cast<float4*>(&Bs[kr][bc4 * 4]) = v;
        }
        __syncthreads();

        #pragma unroll
        for (int k = 0; k < 16; k++) {
            float a[8], b[8];
            #pragma unroll
            for (int i = 0; i < 8; i++) a[i] = As[k][ty * 8 + i];
            #pragma unroll
            for (int j = 0; j < 8; j++) b[j] = Bs[k][tx * 8 + j];
            #pragma unroll
            for (int i = 0; i < 8; i++)
                #pragma unroll
                for (int j = 0; j < 8; j++)
                    acc[i][j] = fmaf(a[i], b[j], acc[i][j]);
        }
        __syncthreads();
    }

    #pragma unroll
    for (int i = 0; i < 8; i++) {
        int row = bm + ty * 8 + i;
        #pragma unroll
        for (int j = 0; j < 8; j += 4) {
            float4 v = make_float4(acc[i][j], acc[i][j + 1], acc[i][j + 2], acc[i][j + 3]);
            *reinterpret_cast<float4*>(&Ou[(size_t)row * CDIM + bn + tx * 8 + j]) = v;
        }
    }
}

// ---------------------------------------------------------------------------
// Kernel 2: scores[bh][m][n] = scale * dot(Q[b,m,h,:], K[b,n,h,:])
// 64x64 output tile per block, full D=64 in one shot.
// ---------------------------------------------------------------------------
__global__ __launch_bounds__(256) void scores_kernel()
{
    const int bh = blockIdx.z;
    const int b  = bh / NHEAD;
    const int h  = bh % NHEAD;
    const float* Q  = g_q + (size_t)b * SEQ * CDIM + h * HDIM;
    const float* K  = g_k + (size_t)b * SEQ * CDIM + h * HDIM;
    float*       Sc = g_scores + (size_t)bh * SEQ * SEQ;

    __shared__ float Qst[64][68];   // Qst[d][m]
    __shared__ float Kst[64][68];   // Kst[d][n]

    const int q0  = blockIdx.y * 64;
    const int n0  = blockIdx.x * 64;
    const int tid = threadIdx.x;
    const int tx  = tid & 15;
    const int ty  = tid >> 4;

    #pragma unroll
    for (int it = 0; it < 4; it++) {
        int row = (tid >> 4) + it * 16;   // 0..63
        int c4  = tid & 15;               // 0..15 -> d = c4*4..c4*4+3
        float4 qv = *reinterpret_cast<const float4*>(
            &Q[(size_t)(q0 + row) * CDIM + c4 * 4]);
        Qst[c4 * 4 + 0][row] = qv.x;
        Qst[c4 * 4 + 1][row] = qv.y;
        Qst[c4 * 4 + 2][row] = qv.z;
        Qst[c4 * 4 + 3][row] = qv.w;
        float4 kv = *reinterpret_cast<const float4*>(
            &K[(size_t)(n0 + row) * CDIM + c4 * 4]);
        Kst[c4 * 4 + 0][row] = kv.x;
        Kst[c4 * 4 + 1][row] = kv.y;
        Kst[c4 * 4 + 2][row] = kv.z;
        Kst[c4 * 4 + 3][row] = kv.w;
    }
    __syncthreads();

    float acc[4][4];
    #pragma unroll
    for (int i = 0; i < 4; i++)
        #pragma unroll
        for (int j = 0; j < 4; j++) acc[i][j] = 0.f;

    #pragma unroll 16
    for (int d = 0; d < 64; d++) {
        float4 a = *reinterpret_cast<const float4*>(&Qst[d][ty * 4]);
        float4 bb = *reinterpret_cast<const float4*>(&Kst[d][tx * 4]);
        float av[4] = {a.x, a.y, a.z, a.w};
        float bv[4] = {bb.x, bb.y, bb.z, bb.w};
        #pragma unroll
        for (int i = 0; i < 4; i++)
            #pragma unroll
            for (int j = 0; j < 4; j++)
                acc[i][j] = fmaf(av[i], bv[j], acc[i][j]);
    }

    const float scale = 0.125f;   // 1/sqrt(64)
    #pragma unroll
    for (int i = 0; i < 4; i++) {
        int row = q0 + ty * 4 + i;
        float4 v = make_float4(acc[i][0] * scale, acc[i][1] * scale,
                               acc[i][2] * scale, acc[i][3] * scale);
        *reinterpret_cast<float4*>(&Sc[(size_t)row * SEQ + n0 + tx * 4]) = v;
    }
}

// ---------------------------------------------------------------------------
// Kernel 3: row softmax over g_scores (row length 1024), in place.
// ---------------------------------------------------------------------------
__global__ __launch_bounds__(256) void softmax_kernel()
{
    float* row = g_scores + (size_t)blockIdx.x * SEQ;
    const int tid = threadIdx.x;

    __shared__ float redm[8];
    __shared__ float reds[8];

    float4 v = reinterpret_cast<float4*>(row)[tid];
    float m = fmaxf(fmaxf(v.x, v.y), fmaxf(v.z, v.w));
    #pragma unroll
    for (int o = 16; o > 0; o >>= 1)
        m = fmaxf(m, __shfl_xor_sync(0xffffffffu, m, o));
    if ((tid & 31) == 0) redm[tid >> 5] = m;
    __syncthreads();
    m = redm[0];
    #pragma unroll
    for (int i = 1; i < 8; i++) m = fmaxf(m, redm[i]);

    v.x = __expf(v.x - m);
    v.y = __expf(v.y - m);
    v.z = __expf(v.z - m);
    v.w = __expf(v.w - m);
    float s = v.x + v.y + v.z + v.w;
    #pragma unroll
    for (int o = 16; o > 0; o >>= 1)
        s += __shfl_xor_sync(0xffffffffu, s, o);
    if ((tid & 31) == 0) reds[tid >> 5] = s;
    __syncthreads();
    s = reds[0];
    #pragma unroll
    for (int i = 1; i < 8; i++) s += reds[i];

    float inv = __frcp_rn(s);
    v.x *= inv; v.y *= inv; v.z *= inv; v.w *= inv;
    reinterpret_cast<float4*>(row)[tid] = v;
}

// ---------------------------------------------------------------------------
// Kernel 4: attn[b, m, h*64+n] = sum_k P[bh][m][k] * V[b, k, h*64+n]
// 64(M) x 64(N=full D) tile, BK=16, 256 threads, 4x4 per thread.
// ---------------------------------------------------------------------------
__global__ __launch_bounds__(256) void pv_kernel()
{
    const int bh = blockIdx.y;
    const int b  = bh / NHEAD;
    const int h  = bh % NHEAD;
    const float* P = g_scores + (size_t)bh * SEQ * SEQ;
    const float* V = g_v + (size_t)b * SEQ * CDIM + h * HDIM;
    float*       O = g_attn + (size_t)b * SEQ * CDIM + h * HDIM;

    const int m0  = blockIdx.x * 64;
    const int tid = threadIdx.x;
    const int tx  = tid & 15;
    const int ty  = tid >> 4;

    __shared__ float Pst[16][68];   // Pst[k][m]
    __shared__ float Vs[16][64];    // Vs[k][n]

    float acc[4][4];
    #pragma unroll
    for (int i = 0; i < 4; i++)
        #pragma unroll
        for (int j = 0; j < 4; j++) acc[i][j] = 0.f;

    const int prow = tid >> 2;   // 0..63
    const int pc4  = tid & 3;    // 0..3
    const int vkr  = tid >> 4;   // 0..15
    const int vc4  = tid & 15;   // 0..15

    for (int k0 = 0; k0 < SEQ; k0 += 16) {
        float4 p = *reinterpret_cast<const float4*>(
            &P[(size_t)(m0 + prow) * SEQ + k0 + pc4 * 4]);
        Pst[pc4 * 4 + 0][prow] = p.x;
        Pst[pc4 * 4 + 1][prow] = p.y;
        Pst[pc4 * 4 + 2][prow] = p.z;
        Pst[pc4 * 4 + 3][prow] = p.w;
        float4 vv = *reinterpret_cast<const float4*>(
            &V[(size_t)(k0 + vkr) * CDIM + vc4 * 4]);
        *reinterpret_cast<float4*>(&Vs[vkr][vc4 * 4]) = vv;
        __syncthreads();

        #pragma unroll
        for (int k = 0; k < 16; k++) {
            float4 a = *reinterpret_cast<const float4*>(&Pst[k][ty * 4]);
            float4 bb = *reinterpret_cast<const float4*>(&Vs[k][tx * 4]);
            float av[4] = {a.x, a.y, a.z, a.w};
            float bv[4] = {bb.x, bb.y, bb.z, bb.w};
            #pragma unroll
            for (int i = 0; i < 4; i++)
                #pragma unroll
                for (int j = 0; j < 4; j++)
                    acc[i][j] = fmaf(av[i], bv[j], acc[i][j]);
        }
        __syncthreads();
    }

    #pragma unroll
    for (int i = 0; i < 4; i++) {
        int row = m0 + ty * 4 + i;
        float4 v = make_float4(acc[i][0], acc[i][1], acc[i][2], acc[i][3]);
        *reinterpret_cast<float4*>(&O[(size_t)row * CDIM + tx * 4]) = v;
    }
}

// ---------------------------------------------------------------------------
// Kernel 5: out = attn @ Wo + bo, broadcast each distinct batch to 4 outputs.
// Same SGEMM structure as qkv_gemm.
// ---------------------------------------------------------------------------
__global__ __launch_bounds__(256, 2) void proj_gemm(
    const float* __restrict__ Wo,
    const float* __restrict__ bo,
    float* __restrict__ out)
{
    __shared__ float As[16][128];
    __shared__ float Bs[16][128];

    const int bm  = blockIdx.y * 128;
    const int bn  = blockIdx.x * 128;
    const int tid = threadIdx.x;
    const int tx  = tid & 15;
    const int ty  = tid >> 4;

    float acc[8][8];
    #pragma unroll
    for (int i = 0; i < 8; i++)
        #pragma unroll
        for (int j = 0; j < 8; j++) acc[i][j] = 0.f;

    const int arow0 = tid >> 2;
    const int ac4   = tid & 3;
    const int bk0   = tid >> 5;
    const int bc4   = tid & 31;

    for (int k0 = 0; k0 < CDIM; k0 += 16) {
        #pragma unroll
        for (int half = 0; half < 2; half++) {
            int row = arow0 + half * 64;
            float4 v = *reinterpret_cast<const float4*>(
                &g_attn[(size_t)(bm + row) * CDIM + k0 + ac4 * 4]);
            As[ac4 * 4 + 0][row] = v.x;
            As[ac4 * 4 + 1][row] = v.y;
            As[ac4 * 4 + 2][row] = v.z;
            As[ac4 * 4 + 3][row] = v.w;
        }
        #pragma unroll
        for (int half = 0; half < 2; half++) {
            int kr = bk0 + half * 8;
            float4 v = *reinterpret_cast<const float4*>(
                &Wo[(size_t)(k0 + kr) * CDIM + bn + bc4 * 4]);
            *reinterpret_cast<float4*>(&Bs[kr][bc4 * 4]) = v;
        }
        __syncthreads();

        #pragma unroll
        for (int k = 0; k < 16; k++) {
            float a[8], b[8];
            #pragma unroll
            for (int i = 0; i < 8; i++) a[i] = As[k][ty * 8 + i];
            #pragma unroll
            for (int j = 0; j < 8; j++) b[j] = Bs[k][tx * 8 + j];
            #pragma unroll
            for (int i = 0; i < 8; i++)
                #pragma unroll
                for (int j = 0; j < 8; j++)
                    acc[i][j] = fmaf(a[i], b[j], acc[i][j]);
        }
        __syncthreads();
    }

    float bias[8];
    #pragma unroll
    for (int j = 0; j < 8; j++) bias[j] = bo[bn + tx * 8 + j];

    #pragma unroll
    for (int i = 0; i < 8; i++) {
        int row  = bm + ty * 8 + i;
        int half = row >> 10;        // 0 -> batches 0..3, 1 -> batches 4..7
        int srow = row & 1023;
        #pragma unroll
        for (int j = 0; j < 8; j += 4) {
            float4 v = make_float4(acc[i][j] + bias[j],
                                   acc[i][j + 1] + bias[j + 1],
                                   acc[i][j + 2] + bias[j + 2],
                                   acc[i][j + 3] + bias[j + 3]);
            #pragma unroll
            for (int rep = 0; rep < 4; rep++) {
                size_t off = ((size_t)(half * 4 + rep) * SEQ + srow) * CDIM + bn + tx * 8 + j;
                *reinterpret_cast<float4*>(&out[off]) = v;
            }
        }
    }
}

// ---------------------------------------------------------------------------
extern "C" void kernel_launch(void* const* d_in, const int* in_sizes, int n_in,
                              void* d_out, int out_size)
{
    (void)in_sizes; (void)n_in; (void)out_size;
    const float* hs = (const float*)d_in[0];
    const float* Wq = (const float*)d_in[1];
    const float* Wk = (const float*)d_in[2];
    const float* Wv = (const float*)d_in[3];
    const float* Wo = (const float*)d_in[4];
    const float* bo = (const float*)d_in[5];
    float* out = (float*)d_out;

    qkv_gemm<<<dim3(CDIM / 128, M2 / 128, 3), 256>>>(hs, Wq, Wk, Wv);
    scores_kernel<<<dim3(SEQ / 64, SEQ / 64, BHPAIRS), 256>>>();
    softmax_kernel<<<dim3(BHPAIRS * SEQ), 256>>>();
    pv_kernel<<<dim3(SEQ / 64, BHPAIRS), 256>>>();
    proj_gemm<<<dim3(CDIM / 128, M2 / 128), 256>>>(Wo, bo, out);
}

// round 3
// speedup vs baseline: 1.7911x; 1.7911x over previous
#include <cuda_runtime.h>
#include <cuda_bf16.h>
#include <cstdint>

#define SEQ   1024
#define CDIM  1280
#define NHEAD 20
#define HDIM  64
#define M2    2048
#define BH    40

typedef __nv_bfloat16 bf16;

// ---------------------------------------------------------------------------
// Scratch (__device__ globals; no allocation allowed)
// ---------------------------------------------------------------------------
__device__ bf16 g_xhi[M2 * CDIM];
__device__ bf16 g_xlo[M2 * CDIM];
__device__ bf16 g_wthi[4 * CDIM * CDIM];   // transposed weights [4][N=C][K=C]
__device__ bf16 g_wtlo[4 * CDIM * CDIM];
__device__ bf16 g_qhi[M2 * CDIM];
__device__ bf16 g_qlo[M2 * CDIM];
__device__ bf16 g_khi[M2 * CDIM];
__device__ bf16 g_klo[M2 * CDIM];
__device__ bf16 g_vthi[BH * HDIM * SEQ];   // V transposed: [bh][d][s]
__device__ bf16 g_vtlo[BH * HDIM * SEQ];
__device__ float g_sc[(size_t)BH * SEQ * SEQ];
__device__ bf16 g_phi[BH * SEQ * SEQ];
__device__ bf16 g_plo[BH * SEQ * SEQ];
__device__ bf16 g_ahi[M2 * CDIM];
__device__ bf16 g_alo[M2 * CDIM];

// ---------------------------------------------------------------------------
// HMMA helpers (all baseline PTX, compiles for compute_103)
// ---------------------------------------------------------------------------
__device__ __forceinline__ uint32_t smem_u32(const void* p) {
    uint32_t a;
    asm("{ .reg .u64 t; cvta.to.shared.u64 t, %1; cvt.u32.u64 %0, t; }"
        : "=r"(a) : "l"(p));
    return a;
}

__device__ __forceinline__ void ldm_x4(uint32_t* r, uint32_t a) {
    asm volatile("ldmatrix.sync.aligned.m8n8.x4.shared.b16 {%0,%1,%2,%3}, [%4];"
                 : "=r"(r[0]), "=r"(r[1]), "=r"(r[2]), "=r"(r[3]) : "r"(a));
}

__device__ __forceinline__ void mma16816(float* c, const uint32_t* a,
                                         uint32_t b0, uint32_t b1) {
    asm volatile(
        "mma.sync.aligned.m16n8k16.row.col.f32.bf16.bf16.f32 "
        "{%0,%1,%2,%3}, {%4,%5,%6,%7}, {%8,%9}, {%0,%1,%2,%3};"
        : "+f"(c[0]), "+f"(c[1]), "+f"(c[2]), "+f"(c[3])
        : "r"(a[0]), "r"(a[1]), "r"(a[2]), "r"(a[3]), "r"(b0), "r"(b1));
}

// Smem layout (dynamic, 30720 B total):
//   Ahi @ 0      : 128 rows x stride 40 bf16 (80 B)  = 10240 B
//   Alo @ 10240  : 10240 B
//   Bhi @ 20480  :  64 rows x stride 40               = 5120 B
//   Blo @ 25600  :  5120 B
#define ASTR    40
#define ROWB    80
#define OFF_ALO 10240
#define OFF_BHI 20480
#define OFF_BLO 25600
#define SMEM_BYTES 30720

// ---------------------------------------------------------------------------
// Unified HMMA mainloop.
// Block computes a 128(M) x 64(N) tile: acc += Ahi@Bhi^T + Ahi@Blo^T + Alo@Bhi^T
// A: [128 rows, kTotal] row-major (lda). B: [64 rows, kTotal] row-major (ldb).
// ---------------------------------------------------------------------------
__device__ __forceinline__ void hmma_mainloop(
    const bf16* __restrict__ Ahi, const bf16* __restrict__ Alo, int lda,
    const bf16* __restrict__ Bhi, const bf16* __restrict__ Blo, int ldb,
    int kTotal, float acc[2][4][4])
{
    extern __shared__ char smem[];
    const uint32_t sb = smem_u32(smem);
    const int tid  = threadIdx.x;
    const int lane = tid & 31;
    const int wid  = tid >> 5;
    const int wm   = wid & 3;      // 0..3  (m offset 32*wm)
    const int wn   = wid >> 2;     // 0..1  (n offset 32*wn)

    #pragma unroll
    for (int i = 0; i < 2; i++)
        #pragma unroll
        for (int t = 0; t < 4; t++)
            #pragma unroll
            for (int u = 0; u < 4; u++) acc[i][t][u] = 0.f;

    // ldmatrix source addresses (per-thread, fixed; kb adds byte offset)
    const uint32_t aAddr = sb + (uint32_t)(wm * 32 + (lane & 15)) * ROWB
                              + ((lane >> 4) << 4);                 // +16B for col8
    const uint32_t bRow  = (uint32_t)(wn * 32 + ((lane >> 4) << 3) + (lane & 7));
    const uint32_t bAddr = sb + OFF_BHI + bRow * ROWB + (((lane >> 3) & 1) << 4);

    // global load indices
    const int ar  = tid >> 1;            // A row pairs: each thread does rows via idx
    const int br  = tid >> 2;            // B rows

    for (int k0 = 0; k0 < kTotal; k0 += 32) {
        // --- load A tiles: 128 rows x 32 bf16 (64 B = 4 uint4 per row) ---
        #pragma unroll
        for (int u = 0; u < 2; u++) {
            int idx = tid * 2 + u;           // 0..511
            int r = idx >> 2, cc = idx & 3;
            uint32_t off = (uint32_t)(r * ROWB + cc * 16);
            *reinterpret_cast<uint4*>(smem + off) =
                *reinterpret_cast<const uint4*>(Ahi + (size_t)r * lda + k0 + cc * 8);
            *reinterpret_cast<uint4*>(smem + OFF_ALO + off) =
                *reinterpret_cast<const uint4*>(Alo + (size_t)r * lda + k0 + cc * 8);
        }
        // --- load B tiles: 64 rows x 32 bf16 ---
        {
            int r = br, cc = tid & 3;        // 256 threads cover 64x4
            uint32_t off = (uint32_t)(r * ROWB + cc * 16);
            *reinterpret_cast<uint4*>(smem + OFF_BHI + off) =
                *reinterpret_cast<const uint4*>(Bhi + (size_t)r * ldb + k0 + cc * 8);
            *reinterpret_cast<uint4*>(smem + OFF_BLO + off) =
                *reinterpret_cast<const uint4*>(Blo + (size_t)r * ldb + k0 + cc * 8);
        }
        __syncthreads();

        #pragma unroll
        for (int kb = 0; kb < 2; kb++) {
            const uint32_t koff = kb * 32;   // 16 bf16 = 32 B
            uint32_t ah[2][4], al[2][4];
            ldm_x4(ah[0], aAddr + koff);
            ldm_x4(ah[1], aAddr + 16 * ROWB + koff);
            ldm_x4(al[0], aAddr + OFF_ALO + koff);
            ldm_x4(al[1], aAddr + OFF_ALO + 16 * ROWB + koff);
            uint32_t bh[2][4], bl[2][4];
            ldm_x4(bh[0], bAddr + koff);
            ldm_x4(bh[1], bAddr + 16 * ROWB + koff);
            ldm_x4(bl[0], bAddr + (OFF_BLO - OFF_BHI) + koff);
            ldm_x4(bl[1], bAddr + (OFF_BLO - OFF_BHI) + 16 * ROWB + koff);

            #pragma unroll
            for (int im = 0; im < 2; im++) {
                #pragma unroll
                for (int p = 0; p < 2; p++) {
                    #pragma unroll
                    for (int q = 0; q < 2; q++) {
                        const int t = p * 2 + q;
                        mma16816(acc[im][t], ah[im], bh[p][2 * q], bh[p][2 * q + 1]);
                        mma16816(acc[im][t], ah[im], bl[p][2 * q], bl[p][2 * q + 1]);
                        mma16816(acc[im][t], al[im], bh[p][2 * q], bh[p][2 * q + 1]);
                    }
                }
            }
        }
        __syncthreads();
    }
}

__device__ __forceinline__ void split2(bf16* __restrict__ Dhi, bf16* __restrict__ Dlo,
                                       size_t o, float f0, float f1) {
    bf16 h0 = __float2bfloat16(f0), h1 = __float2bfloat16(f1);
    bf16 l0 = __float2bfloat16(f0 - __bfloat162float(h0));
    bf16 l1 = __float2bfloat16(f1 - __bfloat162float(h1));
    __nv_bfloat162 hv; hv.x = h0; hv.y = h1;
    __nv_bfloat162 lv; lv.x = l0; lv.y = l1;
    *reinterpret_cast<__nv_bfloat162*>(Dhi + o) = hv;
    *reinterpret_cast<__nv_bfloat162*>(Dlo + o) = lv;
}

// ---------------------------------------------------------------------------
// Stage 0a: convert hidden states (batches 0 and 4) to bf16 hi/lo
// ---------------------------------------------------------------------------
__global__ __launch_bounds__(256) void conv_x(const float* __restrict__ X) {
    int i = blockIdx.x * 256 + threadIdx.x;
    int r = i / (CDIM / 4);
    int c = i % (CDIM / 4);
    int srow = (r < SEQ) ? r : r + 3 * SEQ;
    float4 v = reinterpret_cast<const float4*>(X)[(size_t)srow * (CDIM / 4) + c];
    float f[4] = {v.x, v.y, v.z, v.w};
    size_t o = (size_t)r * CDIM + c * 4;
    split2(g_xhi, g_xlo, o,     f[0], f[1]);
    split2(g_xhi, g_xlo, o + 2, f[2], f[3]);
}

// ---------------------------------------------------------------------------
// Stage 0b: transpose + convert weights: Wt[n][k] = W[k][n] as bf16 hi/lo
// ---------------------------------------------------------------------------
__global__ __launch_bounds__(256) void conv_w(const float* __restrict__ Wq,
                                              const float* __restrict__ Wk,
                                              const float* __restrict__ Wv,
                                              const float* __restrict__ Wo) {
    const int z = blockIdx.z;
    const float* W = (z == 0) ? Wq : (z == 1) ? Wk : (z == 2) ? Wv : Wo;
    bf16* Whi = g_wthi + (size_t)z * CDIM * CDIM;
    bf16* Wlo = g_wtlo + (size_t)z * CDIM * CDIM;

    __shared__ float t[32][33];
    int tx = threadIdx.x, ty = threadIdx.y;
    int x = blockIdx.x * 32 + tx;
    int y0 = blockIdx.y * 32;
    #pragma unroll
    for (int j = 0; j < 32; j += 8)
        t[ty + j][tx] = W[(size_t)(y0 + ty + j) * CDIM + x];
    __syncthreads();

    int xo = blockIdx.y * 32 + tx;
    int yo = blockIdx.x * 32;
    #pragma unroll
    for (int j = 0; j < 32; j += 8) {
        float f = t[tx][ty + j];
        bf16 hi = __float2bfloat16(f);
        bf16 lo = __float2bfloat16(f - __bfloat162float(hi));
        size_t o = (size_t)(yo + ty + j) * CDIM + xo;
        Whi[o] = hi;
        Wlo[o] = lo;
    }
}

// ---------------------------------------------------------------------------
// Stage 1: QKV projection. grid (20, 16, 3)
// ---------------------------------------------------------------------------
__global__ __launch_bounds__(256, 2) void qkv_tc() {
    const int z  = blockIdx.z;
    const int bm = blockIdx.y * 128;
    const int bn = blockIdx.x * 64;

    float acc[2][4][4];
    hmma_mainloop(g_xhi + (size_t)bm * CDIM, g_xlo + (size_t)bm * CDIM, CDIM,
                  g_wthi + (size_t)z * CDIM * CDIM + (size_t)bn * CDIM,
                  g_wtlo + (size_t)z * CDIM * CDIM + (size_t)bn * CDIM, CDIM,
                  CDIM, acc);

    const int tid = threadIdx.x, lane = tid & 31, wid = tid >> 5;
    const int wm = wid & 3, wn = wid >> 2;
    const int r0 = bm + wm * 32 + (lane >> 2);
    const int c0 = bn + wn * 32 + (lane & 3) * 2;

    if (z == 2) {
        // V: store transposed hi/lo [bh][d][s]
        #pragma unroll
        for (int im = 0; im < 2; im++) {
            #pragma unroll
            for (int t = 0; t < 4; t++) {
                const int col = c0 + t * 8;
                const int h = col >> 6, d = col & 63;
                #pragma unroll
                for (int half = 0; half < 2; half++) {
                    const int row = r0 + im * 16 + half * 8;
                    const int b = row >> 10, s = row & 1023;
                    const size_t base = ((size_t)(b * NHEAD + h) * HDIM + d) * SEQ + s;
                    float f0 = acc[im][t][half * 2], f1 = acc[im][t][half * 2 + 1];
                    bf16 h0 = __float2bfloat16(f0), h1 = __float2bfloat16(f1);
                    g_vthi[base]       = h0;
                    g_vthi[base + SEQ] = h1;
                    g_vtlo[base]       = __float2bfloat16(f0 - __bfloat162float(h0));
                    g_vtlo[base + SEQ] = __float2bfloat16(f1 - __bfloat162float(h1));
                }
            }
        }
    } else {
        bf16* Dhi = (z == 0) ? g_qhi : g_khi;
        bf16* Dlo = (z == 0) ? g_qlo : g_klo;
        #pragma unroll
        for (int im = 0; im < 2; im++) {
            #pragma unroll
            for (int t = 0; t < 4; t++) {
                const int col = c0 + t * 8;
                const int row = r0 + im * 16;
                split2(Dhi, Dlo, (size_t)row * CDIM + col,
                       acc[im][t][0], acc[im][t][1]);
                split2(Dhi, Dlo, (size_t)(row + 8) * CDIM + col,
                       acc[im][t][2], acc[im][t][3]);
            }
        }
    }
}

// ---------------------------------------------------------------------------
// Stage 2: scores = (Q @ K^T) * scale. grid (16, 8, 40), K=64
// ---------------------------------------------------------------------------
__global__ __launch_bounds__(256, 2) void scores_tc() {
    const int bh = blockIdx.z;
    const int b  = bh / NHEAD;
    const int h  = bh % NHEAD;
    const int bm = blockIdx.y * 128;
    const int bn = blockIdx.x * 64;

    float acc[2][4][4];
    hmma_mainloop(g_qhi + (size_t)(b * SEQ + bm) * CDIM + h * HDIM,
                  g_qlo + (size_t)(b * SEQ + bm) * CDIM + h * HDIM, CDIM,
                  g_khi + (size_t)(b * SEQ + bn) * CDIM + h * HDIM,
                  g_klo + (size_t)(b * SEQ + bn) * CDIM + h * HDIM, CDIM,
                  HDIM, acc);

    float* Sc = g_sc + (size_t)bh * SEQ * SEQ;
    const int tid = threadIdx.x, lane = tid & 31, wid = tid >> 5;
    const int wm = wid & 3, wn = wid >> 2;
    const int r0 = bm + wm * 32 + (lane >> 2);
    const int c0 = bn + wn * 32 + (lane & 3) * 2;

    #pragma unroll
    for (int im = 0; im < 2; im++) {
        #pragma unroll
        for (int t = 0; t < 4; t++) {
            const int col = c0 + t * 8;
            const int row = r0 + im * 16;
            float2 v0 = make_float2(acc[im][t][0] * 0.125f, acc[im][t][1] * 0.125f);
            float2 v1 = make_float2(acc[im][t][2] * 0.125f, acc[im][t][3] * 0.125f);
            *reinterpret_cast<float2*>(&Sc[(size_t)row * SEQ + col]) = v0;
            *reinterpret_cast<float2*>(&Sc[(size_t)(row + 8) * SEQ + col]) = v1;
        }
    }
}

// ---------------------------------------------------------------------------
// Stage 3: row softmax, fp32 in -> bf16 hi/lo out. grid (40*1024)
// ---------------------------------------------------------------------------
__global__ __launch_bounds__(256) void softmax_hl() {
    const size_t rowi = blockIdx.x;
    const float4* row = reinterpret_cast<const float4*>(g_sc + rowi * SEQ);
    const int tid = threadIdx.x;

    __shared__ float redm[8];
    __shared__ float reds[8];

    float4 v = row[tid];
    float m = fmaxf(fmaxf(v.x, v.y), fmaxf(v.z, v.w));
    #pragma unroll
    for (int o = 16; o > 0; o >>= 1)
        m = fmaxf(m, __shfl_xor_sync(0xffffffffu, m, o));
    if ((tid & 31) == 0) redm[tid >> 5] = m;
    __syncthreads();
    m = redm[0];
    #pragma unroll
    for (int i = 1; i < 8; i++) m = fmaxf(m, redm[i]);

    v.x = __expf(v.x - m);
    v.y = __expf(v.y - m);
    v.z = __expf(v.z - m);
    v.w = __expf(v.w - m);
    float s = v.x + v.y + v.z + v.w;
    #pragma unroll
    for (int o = 16; o > 0; o >>= 1)
        s += __shfl_xor_sync(0xffffffffu, s, o);
    if ((tid & 31) == 0) reds[tid >> 5] = s;
    __syncthreads();
    s = reds[0];
    #pragma unroll
    for (int i = 1; i < 8; i++) s += reds[i];

    const float inv = __frcp_rn(s);
    size_t o = rowi * SEQ + tid * 4;
    split2(g_phi, g_plo, o,     v.x * inv, v.y * inv);
    split2(g_phi, g_plo, o + 2, v.z * inv, v.w * inv);
}

// ---------------------------------------------------------------------------
// Stage 4: attn = P @ V. grid (8, 40). N=64, K=1024
// ---------------------------------------------------------------------------
__global__ __launch_bounds__(256, 2) void pv_tc() {
    const int bh = blockIdx.y;
    const int b  = bh / NHEAD;
    const int h  = bh % NHEAD;
    const int bm = blockIdx.x * 128;

    float acc[2][4][4];
    hmma_mainloop(g_phi + (size_t)bh * SEQ * SEQ + (size_t)bm * SEQ,
                  g_plo + (size_t)bh * SEQ * SEQ + (size_t)bm * SEQ, SEQ,
                  g_vthi + (size_t)bh * HDIM * SEQ,
                  g_vtlo + (size_t)bh * HDIM * SEQ, SEQ,
                  SEQ, acc);

    const int tid = threadIdx.x, lane = tid & 31, wid = tid >> 5;
    const int wm = wid & 3, wn = wid >> 2;
    const int r0 = bm + wm * 32 + (lane >> 2);
    const int c0 = wn * 32 + (lane & 3) * 2;

    #pragma unroll
    for (int im = 0; im < 2; im++) {
        #pragma unroll
        for (int t = 0; t < 4; t++) {
            const int col = h * HDIM + c0 + t * 8;
            const int row = b * SEQ + r0 + im * 16;
            split2(g_ahi, g_alo, (size_t)row * CDIM + col,
                   acc[im][t][0], acc[im][t][1]);
            split2(g_ahi, g_alo, (size_t)(row + 8) * CDIM + col,
                   acc[im][t][2], acc[im][t][3]);
        }
    }
}

// ---------------------------------------------------------------------------
// Stage 5: out = attn @ Wo + bo, broadcast x4 per half. grid (20, 16)
// ---------------------------------------------------------------------------
__global__ __launch_bounds__(256, 2) void proj_tc(const float* __restrict__ bo,
                                                  float* __restrict__ out) {
    const int bm = blockIdx.y * 128;
    const int bn = blockIdx.x * 64;

    float acc[2][4][4];
    hmma_mainloop(g_ahi + (size_t)bm * CDIM, g_alo + (size_t)bm * CDIM, CDIM,
                  g_wthi + (size_t)3 * CDIM * CDIM + (size_t)bn * CDIM,
                  g_wtlo + (size_t)3 * CDIM * CDIM + (size_t)bn * CDIM, CDIM,
                  CDIM, acc);

    const int tid = threadIdx.x, lane = tid & 31, wid = tid >> 5;
    const int wm = wid & 3, wn = wid >> 2;
    const int r0 = bm + wm * 32 + (lane >> 2);
    const int c0 = bn + wn * 32 + (lane & 3) * 2;

    #pragma unroll
    for (int im = 0; im < 2; im++) {
        #pragma unroll
        for (int t = 0; t < 4; t++) {
            const int col = c0 + t * 8;
            const float2 bv = *reinterpret_cast<const float2*>(&bo[col]);
            #pragma unroll
            for (int half = 0; half < 2; half++) {
                const int row = r0 + im * 16 + half * 8;
                const int hb = row >> 10, s = row & 1023;
                float2 v = make_float2(acc[im][t][half * 2] + bv.x,
                                       acc[im][t][half * 2 + 1] + bv.y);
                #pragma unroll
                for (int rep = 0; rep < 4; rep++) {
                    size_t o = ((size_t)(hb * 4 + rep) * SEQ + s) * CDIM + col;
                    *reinterpret_cast<float2*>(&out[o]) = v;
                }
            }
        }
    }
}

// ---------------------------------------------------------------------------
extern "C" void kernel_launch(void* const* d_in, const int* in_sizes, int n_in,
                              void* d_out, int out_size)
{
    (void)in_sizes; (void)n_in; (void)out_size;
    const float* hs = (const float*)d_in[0];
    const float* Wq = (const float*)d_in[1];
    const float* Wk = (const float*)d_in[2];
    const float* Wv = (const float*)d_in[3];
    const float* Wo = (const float*)d_in[4];
    const float* bo = (const float*)d_in[5];
    float* out = (float*)d_out;

    conv_x<<<(M2 * CDIM / 4) / 256, 256>>>(hs);
    conv_w<<<dim3(CDIM / 32, CDIM / 32, 4), dim3(32, 8)>>>(Wq, Wk, Wv, Wo);
    qkv_tc<<<dim3(CDIM / 64, M2 / 128, 3), 256, SMEM_BYTES>>>();
    scores_tc<<<dim3(SEQ / 64, SEQ / 128, BH), 256, SMEM_BYTES>>>();
    softmax_hl<<<BH * SEQ, 256>>>();
    pv_tc<<<dim3(SEQ / 128, BH), 256, SMEM_BYTES>>>();
    proj_tc<<<dim3(CDIM / 64, M2 / 128), 256, SMEM_BYTES>>>(bo, out);
}

// round 5
// speedup vs baseline: 2.1819x; 1.2182x over previous
#include <cuda_runtime.h>
#include <cuda_bf16.h>
#include <cstdint>

#define SEQ   1024
#define CDIM  1280
#define NHEAD 20
#define HDIM  64
#define M2    2048
#define BH    40

typedef __nv_bfloat16 bf16;

// ---------------------------------------------------------------------------
// Scratch (__device__ globals; no allocation allowed)
// ---------------------------------------------------------------------------
__device__ bf16 g_xhi[M2 * CDIM];
__device__ bf16 g_xlo[M2 * CDIM];
__device__ bf16 g_wthi[4 * CDIM * CDIM];   // transposed weights [4][N=C][K=C]
__device__ bf16 g_wtlo[4 * CDIM * CDIM];
__device__ bf16 g_qhi[M2 * CDIM];
__device__ bf16 g_qlo[M2 * CDIM];
__device__ bf16 g_khi[M2 * CDIM];
__device__ bf16 g_klo[M2 * CDIM];
__device__ bf16 g_vthi[BH * HDIM * SEQ];   // V transposed: [bh][d][s]
__device__ bf16 g_vtlo[BH * HDIM * SEQ];
__device__ float g_sc[(size_t)BH * SEQ * SEQ];
__device__ bf16 g_phi[BH * SEQ * SEQ];
__device__ bf16 g_plo[BH * SEQ * SEQ];
__device__ bf16 g_ahi[M2 * CDIM];
__device__ bf16 g_alo[M2 * CDIM];

// ---------------------------------------------------------------------------
// Helpers
// ---------------------------------------------------------------------------
__device__ __forceinline__ uint32_t smem_u32(const void* p) {
    uint32_t a;
    asm("{ .reg .u64 t; cvta.to.shared.u64 t, %1; cvt.u32.u64 %0, t; }"
        : "=r"(a) : "l"(p));
    return a;
}

__device__ __forceinline__ void ldm_x4(uint32_t* r, uint32_t a) {
    asm volatile("ldmatrix.sync.aligned.m8n8.x4.shared.b16 {%0,%1,%2,%3}, [%4];"
                 : "=r"(r[0]), "=r"(r[1]), "=r"(r[2]), "=r"(r[3]) : "r"(a));
}

__device__ __forceinline__ void mma16816(float* c, const uint32_t* a,
                                         uint32_t b0, uint32_t b1) {
    asm volatile(
        "mma.sync.aligned.m16n8k16.row.col.f32.bf16.bf16.f32 "
        "{%0,%1,%2,%3}, {%4,%5,%6,%7}, {%8,%9}, {%0,%1,%2,%3};"
        : "+f"(c[0]), "+f"(c[1]), "+f"(c[2]), "+f"(c[3])
        : "r"(a[0]), "r"(a[1]), "r"(a[2]), "r"(a[3]), "r"(b0), "r"(b1));
}

__device__ __forceinline__ void cp16(uint32_t dst, const void* src) {
    asm volatile("cp.async.cg.shared.global [%0], [%1], 16;"
                 :: "r"(dst), "l"(src));
}

// Per-buffer smem layout (30720 B), double-buffered (61440 B total):
//   Ahi @ 0      : 128 rows x stride 40 bf16 (80 B)  = 10240 B
//   Alo @ 10240  : 10240 B
//   Bhi @ 20480  :  64 rows x stride 40               = 5120 B
//   Blo @ 25600  :  5120 B
#define ROWB    80
#define OFF_ALO 10240
#define OFF_BHI 20480
#define OFF_BLO 25600
#define BUFSZ   30720
#define SMEM_BYTES (2 * BUFSZ)

// ---------------------------------------------------------------------------
// Double-buffered cp.async HMMA mainloop.
// Block computes 128(M) x 64(N): acc += Ahi@Bhi^T + Ahi@Blo^T + Alo@Bhi^T
// A: [128, kTotal] row-major (lda). B: [64, kTotal] row-major (ldb).
// ---------------------------------------------------------------------------
__device__ __forceinline__ void hmma_mainloop(
    const bf16* __restrict__ Ahi, const bf16* __restrict__ Alo, int lda,
    const bf16* __restrict__ Bhi, const bf16* __restrict__ Blo, int ldb,
    int kTotal, float acc[2][4][4])
{
    extern __shared__ char smem[];
    const uint32_t sb = smem_u32(smem);
    const int tid  = threadIdx.x;
    const int lane = tid & 31;
    const int wid  = tid >> 5;
    const int wm   = wid & 3;
    const int wn   = wid >> 2;

    #pragma unroll
    for (int i = 0; i < 2; i++)
        #pragma unroll
        for (int t = 0; t < 4; t++)
            #pragma unroll
            for (int u = 0; u < 4; u++) acc[i][t][u] = 0.f;

    // per-thread cp.async targets: A rows via (tid>>1), B rows via (tid>>2)
    const int arow = tid >> 1;
    const int ac0  = (tid & 1) * 2;       // cc base; loads cc, cc+1 (16B each)
    const int brow = tid >> 2;
    const int bcc  = tid & 3;

    const uint32_t aSm = (uint32_t)(arow * ROWB + ac0 * 16);
    const uint32_t bSm = (uint32_t)(OFF_BHI + brow * ROWB + bcc * 16);
    const bf16* aHiP = Ahi + (size_t)arow * lda + ac0 * 8;
    const bf16* aLoP = Alo + (size_t)arow * lda + ac0 * 8;
    const bf16* bHiP = Bhi + (size_t)brow * ldb + bcc * 8;
    const bf16* bLoP = Blo + (size_t)brow * ldb + bcc * 8;

    // ldmatrix source addresses (fixed part; buffer offset added per iter)
    const uint32_t aAddr = sb + (uint32_t)(wm * 32 + (lane & 15)) * ROWB
                              + ((lane >> 4) << 4);
    const uint32_t bRow  = (uint32_t)(wn * 32 + ((lane >> 4) << 3) + (lane & 7));
    const uint32_t bAddr = sb + OFF_BHI + bRow * ROWB + (((lane >> 3) & 1) << 4);

    const int iters = kTotal >> 5;

#define ISSUE_TILE(IT) do {                                                    \
        const int k0_ = (IT) * 32;                                             \
        const uint32_t bo_ = (uint32_t)(((IT) & 1) * BUFSZ);                   \
        cp16(sb + bo_ + aSm,                aHiP + k0_);                       \
        cp16(sb + bo_ + aSm + 16,           aHiP + k0_ + 8);                   \
        cp16(sb + bo_ + aSm + OFF_ALO,      aLoP + k0_);                       \
        cp16(sb + bo_ + aSm + OFF_ALO + 16, aLoP + k0_ + 8);                   \
        cp16(sb + bo_ + bSm,                      bHiP + k0_);                 \
        cp16(sb + bo_ + bSm + (OFF_BLO-OFF_BHI),  bLoP + k0_);                 \
        asm volatile("cp.async.commit_group;" ::: "memory");                   \
    } while (0)

    ISSUE_TILE(0);

    for (int it = 0; it < iters; it++) {
        if (it + 1 < iters) {
            ISSUE_TILE(it + 1);
            asm volatile("cp.async.wait_group 1;" ::: "memory");
        } else {
            asm volatile("cp.async.wait_group 0;" ::: "memory");
        }
        __syncthreads();

        const uint32_t bufOff = (uint32_t)((it & 1) * BUFSZ);
        #pragma unroll
        for (int kb = 0; kb < 2; kb++) {
            const uint32_t koff = bufOff + kb * 32;   // 16 bf16 = 32 B
            uint32_t ah[2][4], al[2][4];
            ldm_x4(ah[0], aAddr + koff);
            ldm_x4(ah[1], aAddr + 16 * ROWB + koff);
            ldm_x4(al[0], aAddr + OFF_ALO + koff);
            ldm_x4(al[1], aAddr + OFF_ALO + 16 * ROWB + koff);
            uint32_t bh[2][4], bl[2][4];
            ldm_x4(bh[0], bAddr + koff);
            ldm_x4(bh[1], bAddr + 16 * ROWB + koff);
            ldm_x4(bl[0], bAddr + (OFF_BLO - OFF_BHI) + koff);
            ldm_x4(bl[1], bAddr + (OFF_BLO - OFF_BHI) + 16 * ROWB + koff);

            #pragma unroll
            for (int im = 0; im < 2; im++) {
                #pragma unroll
                for (int p = 0; p < 2; p++) {
                    #pragma unroll
                    for (int q = 0; q < 2; q++) {
                        const int t = p * 2 + q;
                        mma16816(acc[im][t], ah[im], bh[p][2 * q], bh[p][2 * q + 1]);
                        mma16816(acc[im][t], ah[im], bl[p][2 * q], bl[p][2 * q + 1]);
                        mma16816(acc[im][t], al[im], bh[p][2 * q], bh[p][2 * q + 1]);
                    }
                }
            }
        }
        __syncthreads();
    }
#undef ISSUE_TILE
}

__device__ __forceinline__ void split2(bf16* __restrict__ Dhi, bf16* __restrict__ Dlo,
                                       size_t o, float f0, float f1) {
    bf16 h0 = __float2bfloat16(f0), h1 = __float2bfloat16(f1);
    bf16 l0 = __float2bfloat16(f0 - __bfloat162float(h0));
    bf16 l1 = __float2bfloat16(f1 - __bfloat162float(h1));
    __nv_bfloat162 hv; hv.x = h0; hv.y = h1;
    __nv_bfloat162 lv; lv.x = l0; lv.y = l1;
    *reinterpret_cast<__nv_bfloat162*>(Dhi + o) = hv;
    *reinterpret_cast<__nv_bfloat162*>(Dlo + o) = lv;
}

// ---------------------------------------------------------------------------
// Stage 0a: convert hidden states (batches 0 and 4) to bf16 hi/lo
// ---------------------------------------------------------------------------
__global__ __launch_bounds__(256) void conv_x(const float* __restrict__ X) {
    int i = blockIdx.x * 256 + threadIdx.x;
    int r = i / (CDIM / 4);
    int c = i % (CDIM / 4);
    int srow = (r < SEQ) ? r : r + 3 * SEQ;
    float4 v = reinterpret_cast<const float4*>(X)[(size_t)srow * (CDIM / 4) + c];
    size_t o = (size_t)r * CDIM + c * 4;
    split2(g_xhi, g_xlo, o,     v.x, v.y);
    split2(g_xhi, g_xlo, o + 2, v.z, v.w);
}

// ---------------------------------------------------------------------------
// Stage 0b: transpose + convert weights: Wt[n][k] = W[k][n] as bf16 hi/lo
// ---------------------------------------------------------------------------
__global__ __launch_bounds__(256) void conv_w(const float* __restrict__ Wq,
                                              const float* __restrict__ Wk,
                                              const float* __restrict__ Wv,
                                              const float* __restrict__ Wo) {
    const int z = blockIdx.z;
    const float* W = (z == 0) ? Wq : (z == 1) ? Wk : (z == 2) ? Wv : Wo;
    bf16* Whi = g_wthi + (size_t)z * CDIM * CDIM;
    bf16* Wlo = g_wtlo + (size_t)z * CDIM * CDIM;

    __shared__ float t[32][33];
    int tx = threadIdx.x, ty = threadIdx.y;
    int x = blockIdx.x * 32 + tx;
    int y0 = blockIdx.y * 32;
    #pragma unroll
    for (int j = 0; j < 32; j += 8)
        t[ty + j][tx] = W[(size_t)(y0 + ty + j) * CDIM + x];
    __syncthreads();

    int xo = blockIdx.y * 32 + tx;
    int yo = blockIdx.x * 32;
    #pragma unroll
    for (int j = 0; j < 32; j += 8) {
        float f = t[tx][ty + j];
        bf16 hi = __float2bfloat16(f);
        bf16 lo = __float2bfloat16(f - __bfloat162float(hi));
        size_t o = (size_t)(yo + ty + j) * CDIM + xo;
        Whi[o] = hi;
        Wlo[o] = lo;
    }
}

// ---------------------------------------------------------------------------
// Stage 1: QKV projection. grid (20, 16, 3)
// ---------------------------------------------------------------------------
__global__ __launch_bounds__(256, 2) void qkv_tc() {
    const int z  = blockIdx.z;
    const int bm = blockIdx.y * 128;
    const int bn = blockIdx.x * 64;

    float acc[2][4][4];
    hmma_mainloop(g_xhi + (size_t)bm * CDIM, g_xlo + (size_t)bm * CDIM, CDIM,
                  g_wthi + (size_t)z * CDIM * CDIM + (size_t)bn * CDIM,
                  g_wtlo + (size_t)z * CDIM * CDIM + (size_t)bn * CDIM, CDIM,
                  CDIM, acc);

    const int tid = threadIdx.x, lane = tid & 31, wid = tid >> 5;
    const int wm = wid & 3, wn = wid >> 2;
    const int r0 = bm + wm * 32 + (lane >> 2);
    const int c0 = bn + wn * 32 + (lane & 3) * 2;

    if (z == 2) {
        #pragma unroll
        for (int im = 0; im < 2; im++) {
            #pragma unroll
            for (int t = 0; t < 4; t++) {
                const int col = c0 + t * 8;
                const int h = col >> 6, d = col & 63;
                #pragma unroll
                for (int half = 0; half < 2; half++) {
                    const int row = r0 + im * 16 + half * 8;
                    const int b = row >> 10, s = row & 1023;
                    const size_t base = ((size_t)(b * NHEAD + h) * HDIM + d) * SEQ + s;
                    float f0 = acc[im][t][half * 2], f1 = acc[im][t][half * 2 + 1];
                    bf16 h0 = __float2bfloat16(f0), h1 = __float2bfloat16(f1);
                    g_vthi[base]       = h0;
                    g_vthi[base + SEQ] = h1;
                    g_vtlo[base]       = __float2bfloat16(f0 - __bfloat162float(h0));
                    g_vtlo[base + SEQ] = __float2bfloat16(f1 - __bfloat162float(h1));
                }
            }
        }
    } else {
        bf16* Dhi = (z == 0) ? g_qhi : g_khi;
        bf16* Dlo = (z == 0) ? g_qlo : g_klo;
        #pragma unroll
        for (int im = 0; im < 2; im++) {
            #pragma unroll
            for (int t = 0; t < 4; t++) {
                const int col = c0 + t * 8;
                const int row = r0 + im * 16;
                split2(Dhi, Dlo, (size_t)row * CDIM + col,
                       acc[im][t][0], acc[im][t][1]);
                split2(Dhi, Dlo, (size_t)(row + 8) * CDIM + col,
                       acc[im][t][2], acc[im][t][3]);
            }
        }
    }
}

// ---------------------------------------------------------------------------
// Stage 2: scores = (Q @ K^T) * scale. grid (16, 8, 40), K=64
// ---------------------------------------------------------------------------
__global__ __launch_bounds__(256, 2) void scores_tc() {
    const int bh = blockIdx.z;
    const int b  = bh / NHEAD;
    const int h  = bh % NHEAD;
    const int bm = blockIdx.y * 128;
    const int bn = blockIdx.x * 64;

    float acc[2][4][4];
    hmma_mainloop(g_qhi + (size_t)(b * SEQ + bm) * CDIM + h * HDIM,
                  g_qlo + (size_t)(b * SEQ + bm) * CDIM + h * HDIM, CDIM,
                  g_khi + (size_t)(b * SEQ + bn) * CDIM + h * HDIM,
                  g_klo + (size_t)(b * SEQ + bn) * CDIM + h * HDIM, CDIM,
                  HDIM, acc);

    float* Sc = g_sc + (size_t)bh * SEQ * SEQ;
    const int tid = threadIdx.x, lane = tid & 31, wid = tid >> 5;
    const int wm = wid & 3, wn = wid >> 2;
    const int r0 = bm + wm * 32 + (lane >> 2);
    const int c0 = bn + wn * 32 + (lane & 3) * 2;

    #pragma unroll
    for (int im = 0; im < 2; im++) {
        #pragma unroll
        for (int t = 0; t < 4; t++) {
            const int col = c0 + t * 8;
            const int row = r0 + im * 16;
            float2 v0 = make_float2(acc[im][t][0] * 0.125f, acc[im][t][1] * 0.125f);
            float2 v1 = make_float2(acc[im][t][2] * 0.125f, acc[im][t][3] * 0.125f);
            *reinterpret_cast<float2*>(&Sc[(size_t)row * SEQ + col]) = v0;
            *reinterpret_cast<float2*>(&Sc[(size_t)(row + 8) * SEQ + col]) = v1;
        }
    }
}

// ---------------------------------------------------------------------------
// Stage 3: row softmax, fp32 in -> bf16 hi/lo out. grid (40*1024)
// ---------------------------------------------------------------------------
__global__ __launch_bounds__(256) void softmax_hl() {
    const size_t rowi = blockIdx.x;
    const float4* row = reinterpret_cast<const float4*>(g_sc + rowi * SEQ);
    const int tid = threadIdx.x;

    __shared__ float redm[8];
    __shared__ float reds[8];

    float4 v = row[tid];
    float m = fmaxf(fmaxf(v.x, v.y), fmaxf(v.z, v.w));
    #pragma unroll
    for (int o = 16; o > 0; o >>= 1)
        m = fmaxf(m, __shfl_xor_sync(0xffffffffu, m, o));
    if ((tid & 31) == 0) redm[tid >> 5] = m;
    __syncthreads();
    m = redm[0];
    #pragma unroll
    for (int i = 1; i < 8; i++) m = fmaxf(m, redm[i]);

    v.x = __expf(v.x - m);
    v.y = __expf(v.y - m);
    v.z = __expf(v.z - m);
    v.w = __expf(v.w - m);
    float s = v.x + v.y + v.z + v.w;
    #pragma unroll
    for (int o = 16; o > 0; o >>= 1)
        s += __shfl_xor_sync(0xffffffffu, s, o);
    if ((tid & 31) == 0) reds[tid >> 5] = s;
    __syncthreads();
    s = reds[0];
    #pragma unroll
    for (int i = 1; i < 8; i++) s += reds[i];

    const float inv = __frcp_rn(s);
    size_t o = rowi * SEQ + tid * 4;
    split2(g_phi, g_plo, o,     v.x * inv, v.y * inv);
    split2(g_phi, g_plo, o + 2, v.z * inv, v.w * inv);
}

// ---------------------------------------------------------------------------
// Stage 4: attn = P @ V. grid (8, 40). N=64, K=1024
// ---------------------------------------------------------------------------
__global__ __launch_bounds__(256, 2) void pv_tc() {
    const int bh = blockIdx.y;
    const int b  = bh / NHEAD;
    const int h  = bh % NHEAD;
    const int bm = blockIdx.x * 128;

    float acc[2][4][4];
    hmma_mainloop(g_phi + (size_t)bh * SEQ * SEQ + (size_t)bm * SEQ,
                  g_plo + (size_t)bh * SEQ * SEQ + (size_t)bm * SEQ, SEQ,
                  g_vthi + (size_t)bh * HDIM * SEQ,
                  g_vtlo + (size_t)bh * HDIM * SEQ, SEQ,
                  SEQ, acc);

    const int tid = threadIdx.x, lane = tid & 31, wid = tid >> 5;
    const int wm = wid & 3, wn = wid >> 2;
    const int r0 = bm + wm * 32 + (lane >> 2);
    const int c0 = wn * 32 + (lane & 3) * 2;

    #pragma unroll
    for (int im = 0; im < 2; im++) {
        #pragma unroll
        for (int t = 0; t < 4; t++) {
            const int col = h * HDIM + c0 + t * 8;
            const int row = b * SEQ + r0 + im * 16;
            split2(g_ahi, g_alo, (size_t)row * CDIM + col,
                   acc[im][t][0], acc[im][t][1]);
            split2(g_ahi, g_alo, (size_t)(row + 8) * CDIM + col,
                   acc[im][t][2], acc[im][t][3]);
        }
    }
}

// ---------------------------------------------------------------------------
// Stage 5: out = attn @ Wo + bo, broadcast x4 per half. grid (20, 16)
// ---------------------------------------------------------------------------
__global__ __launch_bounds__(256, 2) void proj_tc(const float* __restrict__ bo,
                                                  float* __restrict__ out) {
    const int bm = blockIdx.y * 128;
    const int bn = blockIdx.x * 64;

    float acc[2][4][4];
    hmma_mainloop(g_ahi + (size_t)bm * CDIM, g_alo + (size_t)bm * CDIM, CDIM,
                  g_wthi + (size_t)3 * CDIM * CDIM + (size_t)bn * CDIM,
                  g_wtlo + (size_t)3 * CDIM * CDIM + (size_t)bn * CDIM, CDIM,
                  CDIM, acc);

    const int tid = threadIdx.x, lane = tid & 31, wid = tid >> 5;
    const int wm = wid & 3, wn = wid >> 2;
    const int r0 = bm + wm * 32 + (lane >> 2);
    const int c0 = bn + wn * 32 + (lane & 3) * 2;

    #pragma unroll
    for (int im = 0; im < 2; im++) {
        #pragma unroll
        for (int t = 0; t < 4; t++) {
            const int col = c0 + t * 8;
            const float2 bv = *reinterpret_cast<const float2*>(&bo[col]);
            #pragma unroll
            for (int half = 0; half < 2; half++) {
                const int row = r0 + im * 16 + half * 8;
                const int hb = row >> 10, s = row & 1023;
                float2 v = make_float2(acc[im][t][half * 2] + bv.x,
                                       acc[im][t][half * 2 + 1] + bv.y);
                #pragma unroll
                for (int rep = 0; rep < 4; rep++) {
                    size_t o = ((size_t)(hb * 4 + rep) * SEQ + s) * CDIM + col;
                    *reinterpret_cast<float2*>(&out[o]) = v;
                }
            }
        }
    }
}

// ---------------------------------------------------------------------------
extern "C" void kernel_launch(void* const* d_in, const int* in_sizes, int n_in,
                              void* d_out, int out_size)
{
    (void)in_sizes; (void)n_in; (void)out_size;
    const float* hs = (const float*)d_in[0];
    const float* Wq = (const float*)d_in[1];
    const float* Wk = (const float*)d_in[2];
    const float* Wv = (const float*)d_in[3];
    const float* Wo = (const float*)d_in[4];
    const float* bo = (const float*)d_in[5];
    float* out = (float*)d_out;

    static bool attr_done = false;
    if (!attr_done) {
        cudaFuncSetAttribute(qkv_tc,    cudaFuncAttributeMaxDynamicSharedMemorySize, SMEM_BYTES);
        cudaFuncSetAttribute(scores_tc, cudaFuncAttributeMaxDynamicSharedMemorySize, SMEM_BYTES);
        cudaFuncSetAttribute(pv_tc,     cudaFuncAttributeMaxDynamicSharedMemorySize, SMEM_BYTES);
        cudaFuncSetAttribute(proj_tc,   cudaFuncAttributeMaxDynamicSharedMemorySize, SMEM_BYTES);
        attr_done = true;
    }

    conv_x<<<(M2 * CDIM / 4) / 256, 256>>>(hs);
    conv_w<<<dim3(CDIM / 32, CDIM / 32, 4), dim3(32, 8)>>>(Wq, Wk, Wv, Wo);
    qkv_tc<<<dim3(CDIM / 64, M2 / 128, 3), 256, SMEM_BYTES>>>();
    scores_tc<<<dim3(SEQ / 64, SEQ / 128, BH), 256, SMEM_BYTES>>>();
    softmax_hl<<<BH * SEQ, 256>>>();
    pv_tc<<<dim3(SEQ / 128, BH), 256, SMEM_BYTES>>>();
    proj_tc<<<dim3(CDIM / 64, M2 / 128), 256, SMEM_BYTES>>>(bo, out);
}

// round 7
// speedup vs baseline: 2.6031x; 1.1931x over previous
#include <cuda_runtime.h>
#include <cuda_bf16.h>
#include <cstdint>

#define SEQ   1024
#define CDIM  1280
#define NHEAD 20
#define HDIM  64
#define M2    2048
#define BH    40

typedef __nv_bfloat16 bf16;

// ---------------------------------------------------------------------------
// Scratch (__device__ globals; no allocation allowed)
// ---------------------------------------------------------------------------
__device__ bf16 g_xhi[M2 * CDIM];
__device__ bf16 g_xlo[M2 * CDIM];
__device__ bf16 g_wthi[4 * CDIM * CDIM];   // transposed weights [4][N=C][K=C]
__device__ bf16 g_wtlo[4 * CDIM * CDIM];
__device__ bf16 g_qhi[M2 * CDIM];
__device__ bf16 g_qlo[M2 * CDIM];
__device__ bf16 g_khi[M2 * CDIM];
__device__ bf16 g_klo[M2 * CDIM];
__device__ bf16 g_vthi[BH * HDIM * SEQ];   // V transposed: [bh][d][s]
__device__ bf16 g_vtlo[BH * HDIM * SEQ];
__device__ bf16 g_ahi[M2 * CDIM];
__device__ bf16 g_alo[M2 * CDIM];

// ---------------------------------------------------------------------------
// Helpers
// ---------------------------------------------------------------------------
__device__ __forceinline__ uint32_t smem_u32(const void* p) {
    uint32_t a;
    asm("{ .reg .u64 t; cvta.to.shared.u64 t, %1; cvt.u32.u64 %0, t; }"
        : "=r"(a) : "l"(p));
    return a;
}

__device__ __forceinline__ void ldm_x4(uint32_t* r, uint32_t a) {
    asm volatile("ldmatrix.sync.aligned.m8n8.x4.shared.b16 {%0,%1,%2,%3}, [%4];"
                 : "=r"(r[0]), "=r"(r[1]), "=r"(r[2]), "=r"(r[3]) : "r"(a));
}

__device__ __forceinline__ void mma16816(float* c, const uint32_t* a,
                                         uint32_t b0, uint32_t b1) {
    asm volatile(
        "mma.sync.aligned.m16n8k16.row.col.f32.bf16.bf16.f32 "
        "{%0,%1,%2,%3}, {%4,%5,%6,%7}, {%8,%9}, {%0,%1,%2,%3};"
        : "+f"(c[0]), "+f"(c[1]), "+f"(c[2]), "+f"(c[3])
        : "r"(a[0]), "r"(a[1]), "r"(a[2]), "r"(a[3]), "r"(b0), "r"(b1));
}

__device__ __forceinline__ void cp16(uint32_t dst, const void* src) {
    asm volatile("cp.async.cg.shared.global [%0], [%1], 16;"
                 :: "r"(dst), "l"(src));
}

__device__ __forceinline__ void split2(bf16* __restrict__ Dhi, bf16* __restrict__ Dlo,
                                       size_t o, float f0, float f1) {
    bf16 h0 = __float2bfloat16(f0), h1 = __float2bfloat16(f1);
    bf16 l0 = __float2bfloat16(f0 - __bfloat162float(h0));
    bf16 l1 = __float2bfloat16(f1 - __bfloat162float(h1));
    __nv_bfloat162 hv; hv.x = h0; hv.y = h1;
    __nv_bfloat162 lv; lv.x = l0; lv.y = l1;
    *reinterpret_cast<__nv_bfloat162*>(Dhi + o) = hv;
    *reinterpret_cast<__nv_bfloat162*>(Dlo + o) = lv;
}

// pack two floats into bf16x2 hi and lo fragments
__device__ __forceinline__ void hilo_pack(float f0, float f1,
                                          uint32_t& hi, uint32_t& lo) {
    bf16 h0 = __float2bfloat16(f0), h1 = __float2bfloat16(f1);
    bf16 l0 = __float2bfloat16(f0 - __bfloat162float(h0));
    bf16 l1 = __float2bfloat16(f1 - __bfloat162float(h1));
    __nv_bfloat162 hv; hv.x = h0; hv.y = h1;
    __nv_bfloat162 lv; lv.x = l0; lv.y = l1;
    hi = *reinterpret_cast<uint32_t*>(&hv);
    lo = *reinterpret_cast<uint32_t*>(&lv);
}

// ---------------------------------------------------------------------------
// GEMM mainloop (qkv / proj): 128(M) x 64(N), double-buffered cp.async
// ---------------------------------------------------------------------------
#define ROWB    80
#define OFF_ALO 10240
#define OFF_BHI 20480
#define OFF_BLO 25600
#define BUFSZ   30720
#define SMEM_BYTES (2 * BUFSZ)

__device__ __forceinline__ void hmma_mainloop(
    const bf16* __restrict__ Ahi, const bf16* __restrict__ Alo, int lda,
    const bf16* __restrict__ Bhi, const bf16* __restrict__ Blo, int ldb,
    int kTotal, float acc[2][4][4])
{
    extern __shared__ char smem[];
    const uint32_t sb = smem_u32(smem);
    const int tid  = threadIdx.x;
    const int lane = tid & 31;
    const int wid  = tid >> 5;
    const int wm   = wid & 3;
    const int wn   = wid >> 2;

    #pragma unroll
    for (int i = 0; i < 2; i++)
        #pragma unroll
        for (int t = 0; t < 4; t++)
            #pragma unroll
            for (int u = 0; u < 4; u++) acc[i][t][u] = 0.f;

    const int arow = tid >> 1;
    const int ac0  = (tid & 1) * 2;
    const int brow = tid >> 2;
    const int bcc  = tid & 3;

    const uint32_t aSm = (uint32_t)(arow * ROWB + ac0 * 16);
    const uint32_t bSm = (uint32_t)(OFF_BHI + brow * ROWB + bcc * 16);
    const bf16* aHiP = Ahi + (size_t)arow * lda + ac0 * 8;
    const bf16* aLoP = Alo + (size_t)arow * lda + ac0 * 8;
    const bf16* bHiP = Bhi + (size_t)brow * ldb + bcc * 8;
    const bf16* bLoP = Blo + (size_t)brow * ldb + bcc * 8;

    const uint32_t aAddr = sb + (uint32_t)(wm * 32 + (lane & 15)) * ROWB
                              + ((lane >> 4) << 4);
    const uint32_t bRow  = (uint32_t)(wn * 32 + ((lane >> 4) << 3) + (lane & 7));
    const uint32_t bAddr = sb + OFF_BHI + bRow * ROWB + (((lane >> 3) & 1) << 4);

    const int iters = kTotal >> 5;

#define ISSUE_TILE(IT) do {                                                    \
        const int k0_ = (IT) * 32;                                             \
        const uint32_t bo_ = (uint32_t)(((IT) & 1) * BUFSZ);                   \
        cp16(sb + bo_ + aSm,                aHiP + k0_);                       \
        cp16(sb + bo_ + aSm + 16,           aHiP + k0_ + 8);                   \
        cp16(sb + bo_ + aSm + OFF_ALO,      aLoP + k0_);                       \
        cp16(sb + bo_ + aSm + OFF_ALO + 16, aLoP + k0_ + 8);                   \
        cp16(sb + bo_ + bSm,                      bHiP + k0_);                 \
        cp16(sb + bo_ + bSm + (OFF_BLO-OFF_BHI),  bLoP + k0_);                 \
        asm volatile("cp.async.commit_group;" ::: "memory");                   \
    } while (0)

    ISSUE_TILE(0);

    for (int it = 0; it < iters; it++) {
        if (it + 1 < iters) {
            ISSUE_TILE(it + 1);
            asm volatile("cp.async.wait_group 1;" ::: "memory");
        } else {
            asm volatile("cp.async.wait_group 0;" ::: "memory");
        }
        __syncthreads();

        const uint32_t bufOff = (uint32_t)((it & 1) * BUFSZ);
        #pragma unroll
        for (int kb = 0; kb < 2; kb++) {
            const uint32_t koff = bufOff + kb * 32;
            uint32_t ah[2][4], al[2][4];
            ldm_x4(ah[0], aAddr + koff);
            ldm_x4(ah[1], aAddr + 16 * ROWB + koff);
            ldm_x4(al[0], aAddr + OFF_ALO + koff);
            ldm_x4(al[1], aAddr + OFF_ALO + 16 * ROWB + koff);
            uint32_t bh[2][4], bl[2][4];
            ldm_x4(bh[0], bAddr + koff);
            ldm_x4(bh[1], bAddr + 16 * ROWB + koff);
            ldm_x4(bl[0], bAddr + (OFF_BLO - OFF_BHI) + koff);
            ldm_x4(bl[1], bAddr + (OFF_BLO - OFF_BHI) + 16 * ROWB + koff);

            #pragma unroll
            for (int im = 0; im < 2; im++) {
                #pragma unroll
                for (int p = 0; p < 2; p++) {
                    #pragma unroll
                    for (int q = 0; q < 2; q++) {
                        const int t = p * 2 + q;
                        mma16816(acc[im][t], ah[im], bh[p][2 * q], bh[p][2 * q + 1]);
                        mma16816(acc[im][t], ah[im], bl[p][2 * q], bl[p][2 * q + 1]);
                        mma16816(acc[im][t], al[im], bh[p][2 * q], bh[p][2 * q + 1]);
                    }
                }
            }
        }
        __syncthreads();
    }
#undef ISSUE_TILE
}

// ---------------------------------------------------------------------------
// Stage 0a: convert hidden states (batches 0 and 4) to bf16 hi/lo
// ---------------------------------------------------------------------------
__global__ __launch_bounds__(256) void conv_x(const float* __restrict__ X) {
    int i = blockIdx.x * 256 + threadIdx.x;
    int r = i / (CDIM / 4);
    int c = i % (CDIM / 4);
    int srow = (r < SEQ) ? r : r + 3 * SEQ;
    float4 v = reinterpret_cast<const float4*>(X)[(size_t)srow * (CDIM / 4) + c];
    size_t o = (size_t)r * CDIM + c * 4;
    split2(g_xhi, g_xlo, o,     v.x, v.y);
    split2(g_xhi, g_xlo, o + 2, v.z, v.w);
}

// ---------------------------------------------------------------------------
// Stage 0b: transpose + convert weights
// ---------------------------------------------------------------------------
__global__ __launch_bounds__(256) void conv_w(const float* __restrict__ Wq,
                                              const float* __restrict__ Wk,
                                              const float* __restrict__ Wv,
                                              const float* __restrict__ Wo) {
    const int z = blockIdx.z;
    const float* W = (z == 0) ? Wq : (z == 1) ? Wk : (z == 2) ? Wv : Wo;
    bf16* Whi = g_wthi + (size_t)z * CDIM * CDIM;
    bf16* Wlo = g_wtlo + (size_t)z * CDIM * CDIM;

    __shared__ float t[32][33];
    int tx = threadIdx.x, ty = threadIdx.y;
    int x = blockIdx.x * 32 + tx;
    int y0 = blockIdx.y * 32;
    #pragma unroll
    for (int j = 0; j < 32; j += 8)
        t[ty + j][tx] = W[(size_t)(y0 + ty + j) * CDIM + x];
    __syncthreads();

    int xo = blockIdx.y * 32 + tx;
    int yo = blockIdx.x * 32;
    #pragma unroll
    for (int j = 0; j < 32; j += 8) {
        float f = t[tx][ty + j];
        bf16 hi = __float2bfloat16(f);
        bf16 lo = __float2bfloat16(f - __bfloat162float(hi));
        size_t o = (size_t)(yo + ty + j) * CDIM + xo;
        Whi[o] = hi;
        Wlo[o] = lo;
    }
}

// ---------------------------------------------------------------------------
// Stage 1: QKV projection. grid (20, 16, 3)
// ---------------------------------------------------------------------------
__global__ __launch_bounds__(256, 2) void qkv_tc() {
    const int z  = blockIdx.z;
    const int bm = blockIdx.y * 128;
    const int bn = blockIdx.x * 64;

    float acc[2][4][4];
    hmma_mainloop(g_xhi + (size_t)bm * CDIM, g_xlo + (size_t)bm * CDIM, CDIM,
                  g_wthi + (size_t)z * CDIM * CDIM + (size_t)bn * CDIM,
                  g_wtlo + (size_t)z * CDIM * CDIM + (size_t)bn * CDIM, CDIM,
                  CDIM, acc);

    const int tid = threadIdx.x, lane = tid & 31, wid = tid >> 5;
    const int wm = wid & 3, wn = wid >> 2;
    const int r0 = bm + wm * 32 + (lane >> 2);
    const int c0 = bn + wn * 32 + (lane & 3) * 2;

    if (z == 2) {
        #pragma unroll
        for (int im = 0; im < 2; im++) {
            #pragma unroll
            for (int t = 0; t < 4; t++) {
                const int col = c0 + t * 8;
                const int h = col >> 6, d = col & 63;
                #pragma unroll
                for (int half = 0; half < 2; half++) {
                    const int row = r0 + im * 16 + half * 8;
                    const int b = row >> 10, s = row & 1023;
                    const size_t base = ((size_t)(b * NHEAD + h) * HDIM + d) * SEQ + s;
                    float f0 = acc[im][t][half * 2], f1 = acc[im][t][half * 2 + 1];
                    bf16 h0 = __float2bfloat16(f0), h1 = __float2bfloat16(f1);
                    g_vthi[base]       = h0;
                    g_vthi[base + SEQ] = h1;
                    g_vtlo[base]       = __float2bfloat16(f0 - __bfloat162float(h0));
                    g_vtlo[base + SEQ] = __float2bfloat16(f1 - __bfloat162float(h1));
                }
            }
        }
    } else {
        bf16* Dhi = (z == 0) ? g_qhi : g_khi;
        bf16* Dlo = (z == 0) ? g_qlo : g_klo;
        #pragma unroll
        for (int im = 0; im < 2; im++) {
            #pragma unroll
            for (int t = 0; t < 4; t++) {
                const int col = c0 + t * 8;
                const int row = r0 + im * 16;
                split2(Dhi, Dlo, (size_t)row * CDIM + col,
                       acc[im][t][0], acc[im][t][1]);
                split2(Dhi, Dlo, (size_t)(row + 8) * CDIM + col,
                       acc[im][t][2], acc[im][t][3]);
            }
        }
    }
}

// ---------------------------------------------------------------------------
// Fused flash attention: scores + softmax + P@V in one kernel.
// grid (8, 40): 128 Q rows per CTA, loop over 16 KV tiles of 64.
// Each warp owns 16 Q rows (softmax stays intra-warp).
// ---------------------------------------------------------------------------
#define AT_ROWB   144                       // 64 bf16 + pad, conflict-free
#define AT_QLO    18432
#define AT_STAGE0 36864
#define AT_STG    36864
#define AT_KLO    9216
#define AT_VHI    18432
#define AT_VLO    27648
#define AT_SMEM   (AT_STAGE0 + 2 * AT_STG)  // 110592

__global__ __launch_bounds__(256) void attn_fused() {
    extern __shared__ char smem[];
    const uint32_t sb = smem_u32(smem);
    const int tid  = threadIdx.x;
    const int lane = tid & 31;
    const int warp = tid >> 5;
    const int bh = blockIdx.y, b = bh / NHEAD, h = bh % NHEAD;
    const int bm = blockIdx.x * 128;

    const bf16* Qh = g_qhi + (size_t)(b * SEQ + bm) * CDIM + h * HDIM;
    const bf16* Ql = g_qlo + (size_t)(b * SEQ + bm) * CDIM + h * HDIM;
    const bf16* Kh = g_khi + (size_t)(b * SEQ) * CDIM + h * HDIM;
    const bf16* Kl = g_klo + (size_t)(b * SEQ) * CDIM + h * HDIM;
    const bf16* Vh = g_vthi + (size_t)bh * HDIM * SEQ;
    const bf16* Vl = g_vtlo + (size_t)bh * HDIM * SEQ;

    // cp.async index maps
    const int qr = tid >> 1, qc = (tid & 1) * 4;   // Q: 128 rows x 8 chunks
    const int kr = tid >> 2, kc = (tid & 3) * 2;   // K/V: 64 rows x 8 chunks

    // Q tile (hi+lo) + KV stage 0 as one commit group
    #pragma unroll
    for (int u = 0; u < 4; u++) {
        cp16(sb + qr * AT_ROWB + (qc + u) * 16,          Qh + (size_t)qr * CDIM + (qc + u) * 8);
        cp16(sb + AT_QLO + qr * AT_ROWB + (qc + u) * 16, Ql + (size_t)qr * CDIM + (qc + u) * 8);
    }

#define AT_ISSUE(IT) do {                                                       \
        const uint32_t sB_ = sb + AT_STAGE0 + (uint32_t)(((IT) & 1) * AT_STG);  \
        const uint32_t so_ = (uint32_t)(kr * AT_ROWB + kc * 16);                \
        const size_t   ks_ = (size_t)((IT) * 64 + kr);                          \
        cp16(sB_ + so_,                Kh + ks_ * CDIM + kc * 8);               \
        cp16(sB_ + so_ + 16,           Kh + ks_ * CDIM + kc * 8 + 8);           \
        cp16(sB_ + AT_KLO + so_,       Kl + ks_ * CDIM + kc * 8);               \
        cp16(sB_ + AT_KLO + so_ + 16,  Kl + ks_ * CDIM + kc * 8 + 8);           \
        cp16(sB_ + AT_VHI + so_,       Vh + (size_t)kr * SEQ + (IT) * 64 + kc * 8);      \
        cp16(sB_ + AT_VHI + so_ + 16,  Vh + (size_t)kr * SEQ + (IT) * 64 + kc * 8 + 8);  \
        cp16(sB_ + AT_VLO + so_,       Vl + (size_t)kr * SEQ + (IT) * 64 + kc * 8);      \
        cp16(sB_ + AT_VLO + so_ + 16,  Vl + (size_t)kr * SEQ + (IT) * 64 + kc * 8 + 8);  \
        asm volatile("cp.async.commit_group;" ::: "memory");                    \
    } while (0)

    AT_ISSUE(0);   // same group as Q loads

    // operand fragment addresses
    const uint32_t aQbase = sb + (uint32_t)((warp * 16 + (lane & 15)) * AT_ROWB
                                            + ((lane >> 4) << 4));
    const uint32_t bBase  = (uint32_t)((((lane >> 4) << 3) + (lane & 7)) * AT_ROWB
                                       + (((lane >> 3) & 1) << 4));

    float oacc[8][4];
    #pragma unroll
    for (int t = 0; t < 8; t++)
        #pragma unroll
        for (int u = 0; u < 4; u++) oacc[t][u] = 0.f;
    float m0 = -1e30f, m1 = -1e30f, l0 = 0.f, l1 = 0.f;

    for (int it = 0; it < 16; it++) {
        if (it + 1 < 16) {
            AT_ISSUE(it + 1);
            asm volatile("cp.async.wait_group 1;" ::: "memory");
        } else {
            asm volatile("cp.async.wait_group 0;" ::: "memory");
        }
        __syncthreads();

        const uint32_t stg = sb + AT_STAGE0 + (uint32_t)((it & 1) * AT_STG);

        // ---- S = Q @ K^T (3-term hi/lo) ----
        float sacc[8][4];
        #pragma unroll
        for (int t = 0; t < 8; t++)
            #pragma unroll
            for (int u = 0; u < 4; u++) sacc[t][u] = 0.f;

        #pragma unroll
        for (int j = 0; j < 4; j++) {
            uint32_t qh4[4], ql4[4];
            ldm_x4(qh4, aQbase + j * 32);
            ldm_x4(ql4, aQbase + AT_QLO + j * 32);
            #pragma unroll
            for (int p = 0; p < 4; p++) {
                uint32_t kh4[4], kl4[4];
                ldm_x4(kh4, stg + bBase + p * 16 * AT_ROWB + j * 32);
                ldm_x4(kl4, stg + AT_KLO + bBase + p * 16 * AT_ROWB + j * 32);
                mma16816(sacc[2 * p],     qh4, kh4[0], kh4[1]);
                mma16816(sacc[2 * p + 1], qh4, kh4[2], kh4[3]);
                mma16816(sacc[2 * p],     qh4, kl4[0], kl4[1]);
                mma16816(sacc[2 * p + 1], qh4, kl4[2], kl4[3]);
                mma16816(sacc[2 * p],     ql4, kh4[0], kh4[1]);
                mma16816(sacc[2 * p + 1], ql4, kh4[2], kh4[3]);
            }
        }

        // ---- online softmax (rows r = base+g and r+8 per thread) ----
        float tmax0 = -1e30f, tmax1 = -1e30f;
        #pragma unroll
        for (int t = 0; t < 8; t++) {
            #pragma unroll
            for (int u = 0; u < 4; u++) sacc[t][u] *= 0.125f;
            tmax0 = fmaxf(tmax0, fmaxf(sacc[t][0], sacc[t][1]));
            tmax1 = fmaxf(tmax1, fmaxf(sacc[t][2], sacc[t][3]));
        }
        tmax0 = fmaxf(tmax0, __shfl_xor_sync(0xffffffffu, tmax0, 1));
        tmax0 = fmaxf(tmax0, __shfl_xor_sync(0xffffffffu, tmax0, 2));
        tmax1 = fmaxf(tmax1, __shfl_xor_sync(0xffffffffu, tmax1, 1));
        tmax1 = fmaxf(tmax1, __shfl_xor_sync(0xffffffffu, tmax1, 2));

        const float mn0 = fmaxf(m0, tmax0), mn1 = fmaxf(m1, tmax1);
        const float al0 = __expf(m0 - mn0), al1 = __expf(m1 - mn1);
        m0 = mn0; m1 = mn1;

        float rs0 = 0.f, rs1 = 0.f;
        #pragma unroll
        for (int t = 0; t < 8; t++) {
            sacc[t][0] = __expf(sacc[t][0] - mn0);
            sacc[t][1] = __expf(sacc[t][1] - mn0);
            sacc[t][2] = __expf(sacc[t][2] - mn1);
            sacc[t][3] = __expf(sacc[t][3] - mn1);
            rs0 += sacc[t][0] + sacc[t][1];
            rs1 += sacc[t][2] + sacc[t][3];
        }
        l0 = l0 * al0 + rs0;
        l1 = l1 * al1 + rs1;
        #pragma unroll
        for (int t = 0; t < 8; t++) {
            oacc[t][0] *= al0; oacc[t][1] *= al0;
            oacc[t][2] *= al1; oacc[t][3] *= al1;
        }

        // ---- O += P @ V (P split hi/lo in registers) ----
        #pragma unroll
        for (int j = 0; j < 4; j++) {
            uint32_t ph[4], pl[4];
            hilo_pack(sacc[2 * j][0],     sacc[2 * j][1],     ph[0], pl[0]);
            hilo_pack(sacc[2 * j][2],     sacc[2 * j][3],     ph[1], pl[1]);
            hilo_pack(sacc[2 * j + 1][0], sacc[2 * j + 1][1], ph[2], pl[2]);
            hilo_pack(sacc[2 * j + 1][2], sacc[2 * j + 1][3], ph[3], pl[3]);
            #pragma unroll
            for (int p = 0; p < 4; p++) {
                uint32_t vh4[4], vl4[4];
                ldm_x4(vh4, stg + AT_VHI + bBase + p * 16 * AT_ROWB + j * 32);
                ldm_x4(vl4, stg + AT_VLO + bBase + p * 16 * AT_ROWB + j * 32);
                mma16816(oacc[2 * p],     ph, vh4[0], vh4[1]);
                mma16816(oacc[2 * p + 1], ph, vh4[2], vh4[3]);
                mma16816(oacc[2 * p],     ph, vl4[0], vl4[1]);
                mma16816(oacc[2 * p + 1], ph, vl4[2], vl4[3]);
                mma16816(oacc[2 * p],     pl, vh4[0], vh4[1]);
                mma16816(oacc[2 * p + 1], pl, vh4[2], vh4[3]);
            }
        }
        __syncthreads();
    }
#undef AT_ISSUE

    // ---- normalize + write out as hi/lo for proj ----
    l0 += __shfl_xor_sync(0xffffffffu, l0, 1);
    l0 += __shfl_xor_sync(0xffffffffu, l0, 2);
    l1 += __shfl_xor_sync(0xffffffffu, l1, 1);
    l1 += __shfl_xor_sync(0xffffffffu, l1, 2);
    const float inv0 = 1.f / l0, inv1 = 1.f / l1;

    const int row0 = b * SEQ + bm + warp * 16 + (lane >> 2);
    #pragma unroll
    for (int t = 0; t < 8; t++) {
        const int col = h * HDIM + t * 8 + (lane & 3) * 2;
        split2(g_ahi, g_alo, (size_t)row0 * CDIM + col,
               oacc[t][0] * inv0, oacc[t][1] * inv0);
        split2(g_ahi, g_alo, (size_t)(row0 + 8) * CDIM + col,
               oacc[t][2] * inv1, oacc[t][3] * inv1);
    }
}

// ---------------------------------------------------------------------------
// Stage 5: out = attn @ Wo + bo, broadcast x4 per half. grid (20, 16)
// ---------------------------------------------------------------------------
__global__ __launch_bounds__(256, 2) void proj_tc(const float* __restrict__ bo,
                                                  float* __restrict__ out) {
    const int bm = blockIdx.y * 128;
    const int bn = blockIdx.x * 64;

    float acc[2][4][4];
    hmma_mainloop(g_ahi + (size_t)bm * CDIM, g_alo + (size_t)bm * CDIM, CDIM,
                  g_wthi + (size_t)3 * CDIM * CDIM + (size_t)bn * CDIM,
                  g_wtlo + (size_t)3 * CDIM * CDIM + (size_t)bn * CDIM, CDIM,
                  CDIM, acc);

    const int tid = threadIdx.x, lane = tid & 31, wid = tid >> 5;
    const int wm = wid & 3, wn = wid >> 2;
    const int r0 = bm + wm * 32 + (lane >> 2);
    const int c0 = bn + wn * 32 + (lane & 3) * 2;

    #pragma unroll
    for (int im = 0; im < 2; im++) {
        #pragma unroll
        for (int t = 0; t < 4; t++) {
            const int col = c0 + t * 8;
            const float2 bv = *reinterpret_cast<const float2*>(&bo[col]);
            #pragma unroll
            for (int half = 0; half < 2; half++) {
                const int row = r0 + im * 16 + half * 8;
                const int hb = row >> 10, s = row & 1023;
                float2 v = make_float2(acc[im][t][half * 2] + bv.x,
                                       acc[im][t][half * 2 + 1] + bv.y);
                #pragma unroll
                for (int rep = 0; rep < 4; rep++) {
                    size_t o = ((size_t)(hb * 4 + rep) * SEQ + s) * CDIM + col;
                    *reinterpret_cast<float2*>(&out[o]) = v;
                }
            }
        }
    }
}

// ---------------------------------------------------------------------------
extern "C" void kernel_launch(void* const* d_in, const int* in_sizes, int n_in,
                              void* d_out, int out_size)
{
    (void)in_sizes; (void)n_in; (void)out_size;
    const float* hs = (const float*)d_in[0];
    const float* Wq = (const float*)d_in[1];
    const float* Wk = (const float*)d_in[2];
    const float* Wv = (const float*)d_in[3];
    const float* Wo = (const float*)d_in[4];
    const float* bo = (const float*)d_in[5];
    float* out = (float*)d_out;

    static bool attr_done = false;
    if (!attr_done) {
        cudaFuncSetAttribute(qkv_tc,     cudaFuncAttributeMaxDynamicSharedMemorySize, SMEM_BYTES);
        cudaFuncSetAttribute(proj_tc,    cudaFuncAttributeMaxDynamicSharedMemorySize, SMEM_BYTES);
        cudaFuncSetAttribute(attn_fused, cudaFuncAttributeMaxDynamicSharedMemorySize, AT_SMEM);
        attr_done = true;
    }

    conv_x<<<(M2 * CDIM / 4) / 256, 256>>>(hs);
    conv_w<<<dim3(CDIM / 32, CDIM / 32, 4), dim3(32, 8)>>>(Wq, Wk, Wv, Wo);
    qkv_tc<<<dim3(CDIM / 64, M2 / 128, 3), 256, SMEM_BYTES>>>();
    attn_fused<<<dim3(SEQ / 128, BH), 256, AT_SMEM>>>();
    proj_tc<<<dim3(CDIM / 64, M2 / 128), 256, SMEM_BYTES>>>(bo, out);
}